// round 11
// baseline (speedup 1.0000x reference)
#include <cuda_runtime.h>
#include <cuda_bf16.h>
#include <cstdint>

// FM-CTR kernel — R11: 2 independent rows per warp (2x gather streams/warp).
// Evidence: R10 hit 80% occ but DRAM stuck at 60% with ~750ns effective
// per-gather latency => queued-but-unsaturated DRAM. Remedy: more
// independent request streams per warp, same warp count.
//
// Inputs (metadata order):
//  d_in[0]: dense_x     f32 [16384, 13]
//  d_in[1]: discrete_x  i32 [16384, 26]
//  d_in[2]: emb_tables  f32 [26, 50000, 128]
//  d_in[3]: dense_w     f32 [128, 13]
//  d_in[4]: dense_b     f32 [128]
// Output: f32 [16384]
//
// Each warp owns rows 2w and 2w+1. Lane l owns float4 slice [4l,4l+4).
// Gather loop issues 2 address-independent LDG.128 per iteration with
// disjoint accumulators. Dense matvec per row computed first (regs die).

#define N_TABLES 26
#define VOCAB    50000
#define EMBED_DIM 128
#define DENSE_DIM 13
#define BATCH    16384
#define THREADS  128
#define WARPS_PER_BLOCK (THREADS / 32)

__global__ __launch_bounds__(THREADS, 12) void fm_ctr_kernel(
    const float* __restrict__ dense_x,
    const int*   __restrict__ discrete_x,
    const float* __restrict__ emb,
    const float* __restrict__ dense_w,
    const float* __restrict__ dense_b,
    float* __restrict__ out)
{
    const int gwarp = (blockIdx.x * THREADS + threadIdx.x) >> 5;
    const int lane  = threadIdx.x & 31;
    const int r0 = gwarp * 2;
    const int r1 = r0 + 1;
    if (r0 >= BATCH) return;

    // Indices for both rows (lanes 0..25 each), broadcast later via shfl.
    int idx_a = 0, idx_b = 0;
    if (lane < N_TABLES) {
        idx_a = discrete_x[r0 * N_TABLES + lane];
        idx_b = discrete_x[r1 * N_TABLES + lane];
    }

    // ---- Dense matvec for both rows first (registers die before gathers) ----
    float4 sa, qa, sb, qb;
    {
        float xa[DENSE_DIM], xb[DENSE_DIM];
        #pragma unroll
        for (int k = 0; k < DENSE_DIM; k++) {
            xa[k] = __ldg(dense_x + r0 * DENSE_DIM + k);
            xb[k] = __ldg(dense_x + r1 * DENSE_DIM + k);
        }
        float a0 = __ldg(dense_b + 4 * lane + 0);
        float a1 = __ldg(dense_b + 4 * lane + 1);
        float a2 = __ldg(dense_b + 4 * lane + 2);
        float a3 = __ldg(dense_b + 4 * lane + 3);
        float b0 = a0, b1 = a1, b2 = a2, b3 = a3;
        #pragma unroll
        for (int k = 0; k < DENSE_DIM; k++) {
            float w0 = __ldg(dense_w + (4 * lane + 0) * DENSE_DIM + k);
            float w1 = __ldg(dense_w + (4 * lane + 1) * DENSE_DIM + k);
            float w2 = __ldg(dense_w + (4 * lane + 2) * DENSE_DIM + k);
            float w3 = __ldg(dense_w + (4 * lane + 3) * DENSE_DIM + k);
            a0 = fmaf(xa[k], w0, a0);  b0 = fmaf(xb[k], w0, b0);
            a1 = fmaf(xa[k], w1, a1);  b1 = fmaf(xb[k], w1, b1);
            a2 = fmaf(xa[k], w2, a2);  b2 = fmaf(xb[k], w2, b2);
            a3 = fmaf(xa[k], w3, a3);  b3 = fmaf(xb[k], w3, b3);
        }
        sa = make_float4(a0, a1, a2, a3);
        qa = make_float4(a0 * a0, a1 * a1, a2 * a2, a3 * a3);
        sb = make_float4(b0, b1, b2, b3);
        qb = make_float4(b0 * b0, b1 * b1, b2 * b2, b3 * b3);
    }

    // ---- Gather loop: 2 independent streams per iteration ----
    #pragma unroll
    for (int t = 0; t < N_TABLES; t++) {
        int ida = __shfl_sync(0xffffffffu, idx_a, t);
        int idb = __shfl_sync(0xffffffffu, idx_b, t);
        unsigned base = (unsigned)(t * VOCAB * EMBED_DIM);
        float4 va = __ldg(reinterpret_cast<const float4*>(
                        emb + base + ((unsigned)ida << 7)) + lane);
        float4 vb = __ldg(reinterpret_cast<const float4*>(
                        emb + base + ((unsigned)idb << 7)) + lane);
        sa.x += va.x; sa.y += va.y; sa.z += va.z; sa.w += va.w;
        qa.x = fmaf(va.x, va.x, qa.x);
        qa.y = fmaf(va.y, va.y, qa.y);
        qa.z = fmaf(va.z, va.z, qa.z);
        qa.w = fmaf(va.w, va.w, qa.w);
        sb.x += vb.x; sb.y += vb.y; sb.z += vb.z; sb.w += vb.w;
        qb.x = fmaf(vb.x, vb.x, qb.x);
        qb.y = fmaf(vb.y, vb.y, qb.y);
        qb.z = fmaf(vb.z, vb.z, qb.z);
        qb.w = fmaf(vb.w, vb.w, qb.w);
    }

    // FM partials: 0.5 * (S^2 - sumsq) per row
    float fa = 0.5f * ((sa.x * sa.x - qa.x) + (sa.y * sa.y - qa.y) +
                       (sa.z * sa.z - qa.z) + (sa.w * sa.w - qa.w));
    float fb = 0.5f * ((sb.x * sb.x - qb.x) + (sb.y * sb.y - qb.y) +
                       (sb.z * sb.z - qb.z) + (sb.w * sb.w - qb.w));

    #pragma unroll
    for (int o = 16; o > 0; o >>= 1) {
        fa += __shfl_down_sync(0xffffffffu, fa, o);
        fb += __shfl_down_sync(0xffffffffu, fb, o);
    }

    if (lane == 0) {
        out[r0] = fa;
        out[r1] = fb;
    }
}

extern "C" void kernel_launch(void* const* d_in, const int* in_sizes, int n_in,
                              void* d_out, int out_size)
{
    const float* dense_x    = (const float*)d_in[0];
    const int*   discrete_x = (const int*)d_in[1];
    const float* emb        = (const float*)d_in[2];
    const float* dense_w    = (const float*)d_in[3];
    const float* dense_b    = (const float*)d_in[4];
    float* out = (float*)d_out;

    // 2 rows per warp -> BATCH/2 warps total
    const int total_warps = BATCH / 2;                       // 8192
    const int blocks = total_warps / WARPS_PER_BLOCK;        // 2048
    fm_ctr_kernel<<<blocks, THREADS>>>(dense_x, discrete_x, emb,
                                       dense_w, dense_b, out);
}